// round 4
// baseline (speedup 1.0000x reference)
#include <cuda_runtime.h>

#define Bn   2
#define Tn   7
#define Hn   128
#define Wn   128
#define Pn   343            // 7*7*7 taps
#define Un   16
#define HW   (Hn*Wn)        // 16384
#define WT   32             // w-tile per block
#define RL   40             // padded row length (needs >= WT+12 for float4 tail)
#define CSTR (49*RL)        // channel stride in smem (floats)

// Block: one (b, h, 32-wide w tile). 128 threads = 16 u x 8 w-groups.
// Each thread owns ONE u and FOUR contiguous w (float4 filt loads -> LDG.128).
// Fused softmax-without-max single pass: filt (719 MB) streamed exactly once.
//
// R4: software pipeline. Loads for taps 4-6 issue BEFORE compute of taps 0-3;
// loads for next row's taps 0-3 issue BEFORE compute of taps 4-6. Every LDG
// gets a full compute phase of slack -> high MLP, latency hidden.
__global__ __launch_bounds__(128, 6)
void dynfilt_kernel(const float* __restrict__ x,
                    const float* __restrict__ filt,
                    float* __restrict__ out)
{
    __shared__ float sm[3 * CSTR];

    const int bx    = blockIdx.x;
    const int wq    = bx & 3;            // w quarter
    const int h     = (bx >> 2) & 127;   // row
    const int b     = bx >> 9;           // batch
    const int tid   = threadIdx.x;
    const int u     = tid >> 3;          // 0..15
    const int wg    = tid & 7;           // 0..7  -> w0 = 4*wg within tile
    const int wbase = wq * WT;

    // ---- stage x patches: sm[(c*49 + t*7 + kh)*RL + j], j in [0,40), zero pad.
    for (int idx = tid; idx < 3 * 49 * RL; idx += 128) {
        int j   = idx % RL;
        int r   = idx / RL;          // c*49 + row
        int row = r % 49;            // t*7 + kh
        int c   = r / 49;
        int t   = row / 7;
        int kh  = row % 7;
        int gh  = h + kh - 3;
        int gw  = wbase + j - 3;
        float v = 0.f;
        if (j < WT + 6 && (unsigned)gh < (unsigned)Hn && (unsigned)gw < (unsigned)Wn)
            v = x[(((size_t)(b * 3 + c) * Tn + t) * Hn + gh) * Wn + gw];
        sm[idx] = v;
    }
    __syncthreads();

    float acc[3][4] = {{0.f,0.f,0.f,0.f},{0.f,0.f,0.f,0.f},{0.f,0.f,0.f,0.f}};
    float lsum[4]   = {0.f, 0.f, 0.f, 0.f};

    // filt[b, p, u, h, w]; per-tap stride = Un*HW elems (1 MB).
    const size_t TAP = (size_t)Un * HW;
    const float* fp = filt + (((size_t)b * Pn) * Un + (size_t)u) * HW
                           + (size_t)h * Wn + wbase + 4 * wg;

    // prologue: stage taps 0..3 of row 0
    float4 f[4], g[3];
    #pragma unroll
    for (int i = 0; i < 4; ++i)
        f[i] = __ldcs((const float4*)(fp + (size_t)i * TAP));

    #pragma unroll 1
    for (int r = 0; r < 49; ++r) {
        const float* srow = sm + r * RL + 4 * wg;   // 16B aligned (RL*4=160)

        // ---- issue loads for taps 4..6 of this row (consumed in phase B) ----
        #pragma unroll
        for (int i = 0; i < 3; ++i)
            g[i] = __ldcs((const float4*)(fp + (size_t)(4 + i) * TAP));

        // ---- patch window [0..7] for the 3 channels ----
        float pw[3][12];
        #pragma unroll
        for (int c = 0; c < 3; ++c) {
            float4 q0 = *(const float4*)(srow + c * CSTR);
            float4 q1 = *(const float4*)(srow + c * CSTR + 4);
            pw[c][0] = q0.x; pw[c][1] = q0.y; pw[c][2] = q0.z; pw[c][3] = q0.w;
            pw[c][4] = q1.x; pw[c][5] = q1.y; pw[c][6] = q1.z; pw[c][7] = q1.w;
        }

        // ---- phase A compute: taps 0..3 from f (staged a full phase ago) ----
        #pragma unroll
        for (int kw = 0; kw < 4; ++kw) {
            float e0 = __expf(f[kw].x);
            float e1 = __expf(f[kw].y);
            float e2 = __expf(f[kw].z);
            float e3 = __expf(f[kw].w);
            lsum[0] += e0; lsum[1] += e1; lsum[2] += e2; lsum[3] += e3;
            #pragma unroll
            for (int c = 0; c < 3; ++c) {
                acc[c][0] += e0 * pw[c][kw];
                acc[c][1] += e1 * pw[c][kw + 1];
                acc[c][2] += e2 * pw[c][kw + 2];
                acc[c][3] += e3 * pw[c][kw + 3];
            }
        }

        // ---- issue loads for taps 0..3 of NEXT row ----
        const float* fpn = fp + 7 * TAP;
        if (r < 48) {
            #pragma unroll
            for (int i = 0; i < 4; ++i)
                f[i] = __ldcs((const float4*)(fpn + (size_t)i * TAP));
        }

        // ---- patch window [8..11] ----
        #pragma unroll
        for (int c = 0; c < 3; ++c) {
            float4 q2 = *(const float4*)(srow + c * CSTR + 8);
            pw[c][8] = q2.x; pw[c][9] = q2.y; pw[c][10] = q2.z; pw[c][11] = q2.w;
        }

        // ---- phase B compute: taps 4..6 from g ----
        #pragma unroll
        for (int k = 0; k < 3; ++k) {
            int kw = k + 4;
            float e0 = __expf(g[k].x);
            float e1 = __expf(g[k].y);
            float e2 = __expf(g[k].z);
            float e3 = __expf(g[k].w);
            lsum[0] += e0; lsum[1] += e1; lsum[2] += e2; lsum[3] += e3;
            #pragma unroll
            for (int c = 0; c < 3; ++c) {
                acc[c][0] += e0 * pw[c][kw];
                acc[c][1] += e1 * pw[c][kw + 1];
                acc[c][2] += e2 * pw[c][kw + 2];
                acc[c][3] += e3 * pw[c][kw + 3];
            }
        }

        fp = fpn;
    }

    // ---- epilogue: normalize + pixel shuffle ----
    // u -> (ur = u/4, uc = u%4); thread w's are wbase+4wg+i.
    const int ur = u >> 2, uc = u & 3;
    const int Ho = Hn * 4, Wo = Wn * 4;
    const size_t cstride = (size_t)Ho * Wo;
    size_t obase = ((size_t)(b * 3) * Ho + (4 * h + ur)) * Wo
                 + (size_t)4 * (wbase + 4 * wg) + uc;

    #pragma unroll
    for (int i = 0; i < 4; ++i) {
        float inv = 1.f / lsum[i];
        out[obase + 4 * i]                = acc[0][i] * inv;
        out[obase + 4 * i + cstride]      = acc[1][i] * inv;
        out[obase + 4 * i + 2 * cstride]  = acc[2][i] * inv;
    }
}

extern "C" void kernel_launch(void* const* d_in, const int* in_sizes, int n_in,
                              void* d_out, int out_size)
{
    const float* x    = (const float*)d_in[0];   // [2,3,7,128,128]
    const float* filt = (const float*)d_in[1];   // [2,343,16,128,128]
    float* out        = (float*)d_out;           // [2,3,512,512]

    dynfilt_kernel<<<Bn * Hn * (Wn / WT), 128>>>(x, filt, out);
}

// round 5
// speedup vs baseline: 1.0267x; 1.0267x over previous
#include <cuda_runtime.h>

#define Bn   2
#define Tn   7
#define Hn   128
#define Wn   128
#define Pn   343            // 7*7*7 taps
#define Un   16
#define HW   (Hn*Wn)        // 16384
#define WT   16             // w-tile per block
#define RL   24             // padded row length (WT+6=22 -> pad 24)
#define CSTR (49*RL)        // channel stride in smem (floats)

// R5: occupancy is the binding resource (DRAM% ~= 1.8 x occ% across R1-R4).
// Go lean: 2 w per thread (float2 loads), WT=16 -> grid 2048 blocks,
// ~50 regs/thread, launch_bounds(128,9) -> 36 warps/SM (56% occ) vs 24.
// Block: one (b, h, 16-wide w tile); 128 threads = 16 u x 8 w-pairs.
// Fused softmax-without-max single pass: filt (719 MB) streamed exactly once.
__global__ __launch_bounds__(128, 9)
void dynfilt_kernel(const float* __restrict__ x,
                    const float* __restrict__ filt,
                    float* __restrict__ out)
{
    __shared__ float sm[3 * CSTR];

    const int bx    = blockIdx.x;
    const int wq    = bx & 7;            // w eighth
    const int h     = (bx >> 3) & 127;   // row
    const int b     = bx >> 10;          // batch
    const int tid   = threadIdx.x;
    const int u     = tid >> 3;          // 0..15
    const int wg    = tid & 7;           // 0..7  -> w0 = 2*wg within tile
    const int wbase = wq * WT;

    // ---- stage x patches: sm[(c*49 + t*7 + kh)*RL + j], j in [0,22), zero pad.
    for (int idx = tid; idx < 3 * 49 * RL; idx += 128) {
        int j   = idx % RL;
        int r   = idx / RL;          // c*49 + row
        int row = r % 49;            // t*7 + kh
        int c   = r / 49;
        int t   = row / 7;
        int kh  = row % 7;
        int gh  = h + kh - 3;
        int gw  = wbase + j - 3;
        float v = 0.f;
        if (j < WT + 6 && (unsigned)gh < (unsigned)Hn && (unsigned)gw < (unsigned)Wn)
            v = x[(((size_t)(b * 3 + c) * Tn + t) * Hn + gh) * Wn + gw];
        sm[idx] = v;
    }
    __syncthreads();

    float acc[3][2] = {{0.f,0.f},{0.f,0.f},{0.f,0.f}};
    float ls0 = 0.f, ls1 = 0.f;

    // filt[b, p, u, h, w]; per-tap stride = Un*HW elems (1 MB).
    const size_t TAP = (size_t)Un * HW;
    const float* fp = filt + (((size_t)b * Pn) * Un + (size_t)u) * HW
                           + (size_t)h * Wn + wbase + 2 * wg;

    #pragma unroll 1
    for (int r = 0; r < 49; ++r) {
        const float* srow = sm + r * RL + 2 * wg;   // 8B aligned

        // ---- front-batch all 7 tap loads of this row (LDG.64) ----
        float2 f[7];
        #pragma unroll
        for (int i = 0; i < 7; ++i)
            f[i] = __ldcs((const float2*)(fp + (size_t)i * TAP));

        // ---- exponentials + denominator ----
        #pragma unroll
        for (int i = 0; i < 7; ++i) {
            f[i].x = __expf(f[i].x);
            f[i].y = __expf(f[i].y);
            ls0 += f[i].x;
            ls1 += f[i].y;
        }

        // ---- per-channel: load 8-float patch window, 7 taps x 2 w FMAs ----
        #pragma unroll
        for (int c = 0; c < 3; ++c) {
            float p[8];
            #pragma unroll
            for (int j = 0; j < 4; ++j) {
                float2 q = *(const float2*)(srow + c * CSTR + 2 * j);
                p[2 * j]     = q.x;
                p[2 * j + 1] = q.y;
            }
            #pragma unroll
            for (int kw = 0; kw < 7; ++kw) {
                acc[c][0] += f[kw].x * p[kw];
                acc[c][1] += f[kw].y * p[kw + 1];
            }
        }

        fp += 7 * TAP;
    }

    // ---- epilogue: normalize + pixel shuffle ----
    // u -> (ur = u/4, uc = u%4); thread w's are wbase+2wg+{0,1}.
    const int ur = u >> 2, uc = u & 3;
    const int Ho = Hn * 4, Wo = Wn * 4;
    const size_t cstride = (size_t)Ho * Wo;
    size_t obase = ((size_t)(b * 3) * Ho + (4 * h + ur)) * Wo
                 + (size_t)4 * (wbase + 2 * wg) + uc;

    const float i0 = 1.f / ls0;
    const float i1 = 1.f / ls1;
    #pragma unroll
    for (int c = 0; c < 3; ++c) {
        out[obase + c * cstride]     = acc[c][0] * i0;
        out[obase + c * cstride + 4] = acc[c][1] * i1;
    }
}

extern "C" void kernel_launch(void* const* d_in, const int* in_sizes, int n_in,
                              void* d_out, int out_size)
{
    const float* x    = (const float*)d_in[0];   // [2,3,7,128,128]
    const float* filt = (const float*)d_in[1];   // [2,343,16,128,128]
    float* out        = (float*)d_out;           // [2,3,512,512]

    // grid = B * H * (W/WT) = 2*128*8 = 2048 blocks, 128 threads each
    dynfilt_kernel<<<Bn * Hn * (Wn / WT), 128>>>(x, filt, out);
}